// round 13
// baseline (speedup 1.0000x reference)
#include <cuda_runtime.h>
#include <cuda_fp16.h>
#include <mma.h>
#include <cstdint>

using namespace nvcuda;

// Problem constants
#define BB 4
#define NN 4096
#define DIMM 1024
#define HH 16
#define HDD 64
#define MM (BB * NN)           // 16384 rows
#define KVC 16                 // kv partial chunks (256 rows each)

// ---------------- scratch (device globals; no allocation allowed) ----------
__device__ __half g_hq[(size_t)MM * DIMM];
__device__ __half g_hk[(size_t)MM * DIMM];
__device__ __half g_hv[(size_t)MM * DIMM];
__device__ __half g_Q16[(size_t)MM * DIMM];
__device__ __half g_K16[(size_t)MM * DIMM];
__device__ __half g_V16[(size_t)MM * DIMM];
__device__ __half g_hA[(size_t)MM * DIMM];
__device__ __half g_Wh[4 * DIMM * DIMM];
__device__ float  g_kvp[(size_t)KVC * BB * HH * HDD * HDD];
__device__ float  g_ksp[(size_t)KVC * BB * HH * HDD];
__device__ float  g_kv[BB * HH * HDD * HDD];
__device__ float  g_ksum[BB * HH * HDD];

__device__ __forceinline__ void cp_async16(void* smem_ptr, const void* gmem_ptr) {
    unsigned int s = (unsigned int)__cvta_generic_to_shared(smem_ptr);
    asm volatile("cp.async.cg.shared.global [%0], [%1], 16;\n" :: "r"(s), "l"(gmem_ptr));
}

// ---------------- fp32 -> fp16 conversion (RN) ----------------
__global__ void cvt_w4(const float* __restrict__ W0, const float* __restrict__ W1,
                       const float* __restrict__ W2, const float* __restrict__ W3,
                       __half* __restrict__ dst) {
    const float* srcs[4] = {W0, W1, W2, W3};
    const int m = blockIdx.y;
    const float4* s = (const float4*)srcs[m];
    __half2* d = (__half2*)(dst + (size_t)m * DIMM * DIMM);
    int i = blockIdx.x * blockDim.x + threadIdx.x;
    if (i < (DIMM * DIMM) / 4) {
        float4 v = s[i];
        d[2 * i + 0] = __floats2half2_rn(v.x, v.y);
        d[2 * i + 1] = __floats2half2_rn(v.z, v.w);
    }
}

__global__ void cvt_acts(const float* __restrict__ A0, const float* __restrict__ A1,
                         const float* __restrict__ A2, __half* __restrict__ D0,
                         __half* __restrict__ D1, __half* __restrict__ D2) {
    const float* srcs[3] = {A0, A1, A2};
    __half* dsts[3] = {D0, D1, D2};
    const int m = blockIdx.y;
    const float4* s = (const float4*)srcs[m];
    __half2* d = (__half2*)dsts[m];
    int i = blockIdx.x * blockDim.x + threadIdx.x;
    if (i < (MM * DIMM) / 4) {
        float4 v = s[i];
        d[2 * i + 0] = __floats2half2_rn(v.x, v.y);
        d[2 * i + 1] = __floats2half2_rn(v.z, v.w);
    }
}

// ==== fp16 GEMM: 128x128 block, 4 warps, 64x64 warp tile, KC=64, 2-stage ===
#define KC 64
#define HPAD 72
#define HTILE (128 * HPAD)
#define HSTAGE (2 * HTILE)
#define GEMM_DSMEM (2 * HSTAGE * 2)        // 73728 bytes
#define GT 128                              // threads per GEMM CTA

extern __shared__ __align__(16) __half dsm_h[];

struct GemmCore {
    wmma::fragment<wmma::accumulator, 16, 16, 16, float> acc[4][4];
    int t, w, wm, wn;

    __device__ __forceinline__ void init(int tid) {
        t = tid; w = t >> 5; wm = w >> 1; wn = w & 1;
#pragma unroll
        for (int i = 0; i < 4; i++)
#pragma unroll
            for (int j = 0; j < 4; j++)
                wmma::fill_fragment(acc[i][j], 0.0f);
    }

    __device__ __forceinline__ void load_chunk(const __half* Abase, const __half* Bbase,
                                               int kc, int s) {
        __half* As = dsm_h + s * HSTAGE;
        __half* Bs = As + HTILE;
        const int k0 = kc * KC;
#pragma unroll
        for (int j = 0; j < 8; j++) {
            int u = t + j * GT;
            int row = u >> 3;
            int c8 = (u & 7) * 8;
            cp_async16(&As[row * HPAD + c8], Abase + (size_t)row * DIMM + k0 + c8);
            cp_async16(&Bs[row * HPAD + c8], Bbase + (size_t)row * DIMM + k0 + c8);
        }
    }

    __device__ __forceinline__ void mainloop(const __half* Abase, const __half* Bbase) {
        load_chunk(Abase, Bbase, 0, 0);
        asm volatile("cp.async.commit_group;\n");
        const int NCH = DIMM / KC;   // 16
        for (int i = 0; i < NCH; i++) {
            const int s = i & 1;
            if (i + 1 < NCH) {
                load_chunk(Abase, Bbase, i + 1, s ^ 1);
                asm volatile("cp.async.commit_group;\n");
                asm volatile("cp.async.wait_group 1;\n");
            } else {
                asm volatile("cp.async.wait_group 0;\n");
            }
            __syncthreads();

            const __half* As = dsm_h + s * HSTAGE;
            const __half* Bs = As + HTILE;
#pragma unroll
            for (int kk = 0; kk < KC; kk += 16) {
                wmma::fragment<wmma::matrix_a, 16, 16, 16, __half, wmma::row_major> af[4];
                wmma::fragment<wmma::matrix_b, 16, 16, 16, __half, wmma::col_major> bf[4];
#pragma unroll
                for (int x = 0; x < 4; x++)
                    wmma::load_matrix_sync(af[x], As + (wm * 64 + x * 16) * HPAD + kk, HPAD);
#pragma unroll
                for (int y = 0; y < 4; y++)
                    wmma::load_matrix_sync(bf[y], Bs + (wn * 64 + y * 16) * HPAD + kk, HPAD);
#pragma unroll
                for (int x = 0; x < 4; x++)
#pragma unroll
                    for (int y = 0; y < 4; y++)
                        wmma::mma_sync(acc[x][y], af[x], bf[y], acc[x][y]);
            }
            __syncthreads();
        }
    }

    __device__ __forceinline__ void epilogue(const float* bias, const int* mask,
                                             float* Cf, __half* Ch, int do_relu,
                                             int m0, int n0) {
        float* Ct = (float*)dsm_h;
#pragma unroll
        for (int half = 0; half < 2; half++) {
            if (wm == half) {
#pragma unroll
                for (int x = 0; x < 4; x++)
#pragma unroll
                    for (int y = 0; y < 4; y++)
                        wmma::store_matrix_sync(Ct + (x * 16) * 132 + wn * 64 + y * 16,
                                                acc[x][y], 132, wmma::mem_row_major);
            }
            __syncthreads();
            // 64x128 floats = 2048 float4, 16 per thread
#pragma unroll
            for (int i = 0; i < 16; i++) {
                int u = t + i * GT;
                int r = u >> 5;
                int c = (u & 31) * 4;
                int row = m0 + half * 64 + r;
                float4 v = *(float4*)(Ct + r * 132 + c);
                v.x += bias[n0 + c + 0];
                v.y += bias[n0 + c + 1];
                v.z += bias[n0 + c + 2];
                v.w += bias[n0 + c + 3];
                if (do_relu) {
                    v.x = fmaxf(v.x, 0.0f); v.y = fmaxf(v.y, 0.0f);
                    v.z = fmaxf(v.z, 0.0f); v.w = fmaxf(v.w, 0.0f);
                }
                if (mask != nullptr && mask[row] != 0) {
                    v.x = 0.0f; v.y = 0.0f; v.z = 0.0f; v.w = 0.0f;
                }
                if (Ch != nullptr) {
                    __half2* p = (__half2*)(Ch + (size_t)row * DIMM + n0 + c);
                    p[0] = __floats2half2_rn(v.x, v.y);
                    p[1] = __floats2half2_rn(v.z, v.w);
                } else {
                    *(float4*)(Cf + (size_t)row * DIMM + n0 + c) = v;
                }
            }
            __syncthreads();
        }
    }
};

// merged Q/K/V projection: blockIdx.z selects matrix
__global__ void __launch_bounds__(GT, 2)
gemm_qkv(const __half* __restrict__ hq, const __half* __restrict__ hk,
         const __half* __restrict__ hv, const __half* __restrict__ Wh,
         const float* __restrict__ bq, const float* __restrict__ bk,
         const float* __restrict__ bv, const int* __restrict__ mask,
         __half* __restrict__ Q16, __half* __restrict__ K16, __half* __restrict__ V16) {
    const int z = blockIdx.z;
    const __half* A = (z == 0) ? hq : (z == 1) ? hk : hv;
    const __half* W = Wh + (size_t)z * DIMM * DIMM;
    const float* bias = (z == 0) ? bq : (z == 1) ? bk : bv;
    const int* mk = (z == 1) ? mask : nullptr;
    __half* out = (z == 0) ? Q16 : (z == 1) ? K16 : V16;
    const int do_relu = (z < 2);

    GemmCore g;
    g.init(threadIdx.x);
    const int n0 = blockIdx.x * 128;
    const int m0 = blockIdx.y * 128;
    g.mainloop(A + (size_t)m0 * DIMM, W + (size_t)n0 * DIMM);
    g.epilogue(bias, mk, nullptr, out, do_relu, m0, n0);
}

// single GEMM (final projection, fp32 out)
__global__ void __launch_bounds__(GT, 2)
gemm_one(const __half* __restrict__ A, const __half* __restrict__ W,
         const float* __restrict__ bias, float* __restrict__ Cf) {
    GemmCore g;
    g.init(threadIdx.x);
    const int n0 = blockIdx.x * 128;
    const int m0 = blockIdx.y * 128;
    g.mainloop(A + (size_t)m0 * DIMM, W + (size_t)n0 * DIMM);
    g.epilogue(bias, nullptr, Cf, nullptr, 0, m0, n0);
}

// ---- kv partials via fp16 WMMA: kvp[c][bh] = K_c^T @ V_c (64x64x256) -----
#define KVPAD 72
__global__ void __launch_bounds__(128)
kv_h(const __half* __restrict__ K, const __half* __restrict__ V,
     float* __restrict__ kvp, float* __restrict__ ksp) {
    __shared__ __align__(16) __half Ks[128][KVPAD];
    __shared__ __align__(16) __half Vs[128][KVPAD];
    __shared__ float ksb[128];

    const int bh = blockIdx.y;
    const int b = bh >> 4, h = bh & 15;
    const int chunk = blockIdx.x;
    const int t = threadIdx.x;
    const int w = t >> 5;
    const int d0 = w * 16;
    const int dcol = t & 63, rhalf = t >> 6;

    wmma::fragment<wmma::accumulator, 16, 16, 16, float> acc[4];
#pragma unroll
    for (int e = 0; e < 4; e++) wmma::fill_fragment(acc[e], 0.0f);
    float ksacc = 0.0f;

#pragma unroll
    for (int sub = 0; sub < 2; sub++) {
        const int n0 = chunk * 256 + sub * 128;
#pragma unroll
        for (int j = 0; j < 8; j++) {
            int u = t + j * 128;
            int row = u >> 3;
            int c8 = (u & 7) * 8;
            const size_t goff = (size_t)(b * NN + n0 + row) * DIMM + h * HDD + c8;
            cp_async16(&Ks[row][c8], K + goff);
            cp_async16(&Vs[row][c8], V + goff);
        }
        asm volatile("cp.async.commit_group;\n");
        asm volatile("cp.async.wait_group 0;\n");
        __syncthreads();

#pragma unroll 16
        for (int r = rhalf * 64; r < rhalf * 64 + 64; r++)
            ksacc += __half2float(Ks[r][dcol]);

#pragma unroll
        for (int ns = 0; ns < 128; ns += 16) {
            wmma::fragment<wmma::matrix_a, 16, 16, 16, __half, wmma::col_major> a;
            wmma::load_matrix_sync(a, &Ks[ns][d0], KVPAD);
#pragma unroll
            for (int e = 0; e < 4; e++) {
                wmma::fragment<wmma::matrix_b, 16, 16, 16, __half, wmma::row_major> bfr;
                wmma::load_matrix_sync(bfr, &Vs[ns][e * 16], KVPAD);
                wmma::mma_sync(acc[e], a, bfr, acc[e]);
            }
        }
        __syncthreads();
    }

    float* dst = kvp + ((size_t)chunk * 64 + bh) * (HDD * HDD);
#pragma unroll
    for (int e = 0; e < 4; e++)
        wmma::store_matrix_sync(dst + d0 * 64 + e * 16, acc[e], 64, wmma::mem_row_major);

    ksb[t] = ksacc;
    __syncthreads();
    if (t < 64) ksp[((size_t)chunk * 64 + bh) * HDD + t] = ksb[t] + ksb[t + 64];
}

// ---- reduce partials ----
__global__ void __launch_bounds__(256)
reduce_kv(const float* __restrict__ kvp, const float* __restrict__ ksp,
          float* __restrict__ kv, float* __restrict__ ksum) {
    const int bh = blockIdx.x;
    const int t = threadIdx.x;
    for (int i = t; i < HDD * HDD; i += 256) {
        float s = 0.0f;
#pragma unroll
        for (int c = 0; c < KVC; c++)
            s += kvp[((size_t)c * 64 + bh) * (HDD * HDD) + i];
        kv[(size_t)bh * (HDD * HDD) + i] = s;
    }
    if (t < 64) {
        float s = 0.0f;
#pragma unroll
        for (int c = 0; c < KVC; c++)
            s += ksp[((size_t)c * 64 + bh) * HDD + t];
        ksum[bh * HDD + t] = s;
    }
}

// ---- out = (q.kv) / (q.ksum + eps); fp16 in, fp16 out ----
__global__ void __launch_bounds__(256)
attn_kernel(const __half* __restrict__ Q, const float* __restrict__ kv,
            const float* __restrict__ ksum, __half* __restrict__ out) {
    const int bh = blockIdx.y;
    const int b = bh >> 4, h = bh & 15;
    const int t = threadIdx.x;
    const int w = t >> 5, l = t & 31;

    __shared__ float kvs[64 * 64];
    __shared__ float kss[64];
    __shared__ float qs[8][64];

    for (int i = t; i < 4096; i += 256) kvs[i] = kv[(size_t)bh * 4096 + i];
    if (t < 64) kss[t] = ksum[bh * 64 + t];
    __syncthreads();

    const int nbase = blockIdx.x * 128;
    for (int it = 0; it < 16; it++) {
        const int n = nbase + it * 8 + w;
        const __half* qrow = Q + ((size_t)(b * NN + n)) * DIMM + h * HDD;
        float q0 = __half2float(qrow[l]);
        float q1 = __half2float(qrow[l + 32]);
        qs[w][l] = q0;
        qs[w][l + 32] = q1;
        __syncwarp();

        float p = q0 * kss[l] + q1 * kss[l + 32];
#pragma unroll
        for (int off = 16; off; off >>= 1) p += __shfl_xor_sync(0xffffffffu, p, off);
        const float denom = 1.0f / (p + 1e-6f);

        float a0 = 0.0f, a1 = 0.0f;
#pragma unroll 8
        for (int d = 0; d < 64; d++) {
            float qd = qs[w][d];
            a0 += qd * kvs[d * 64 + l];
            a1 += qd * kvs[d * 64 + l + 32];
        }
        __half* orow = out + ((size_t)(b * NN + n)) * DIMM + h * HDD;
        orow[l] = __float2half_rn(a0 * denom);
        orow[l + 32] = __float2half_rn(a1 * denom);
        __syncwarp();
    }
}

// ---------------- launch ----------------
extern "C" void kernel_launch(void* const* d_in, const int* in_sizes, int n_in,
                              void* d_out, int out_size) {
    const float* query = (const float*)d_in[0];
    const float* key   = (const float*)d_in[1];
    const float* value = (const float*)d_in[2];
    const float* Wq = (const float*)d_in[3];
    const float* bq = (const float*)d_in[4];
    const float* Wk = (const float*)d_in[5];
    const float* bk = (const float*)d_in[6];
    const float* Wv = (const float*)d_in[7];
    const float* bv = (const float*)d_in[8];
    const float* Wo = (const float*)d_in[9];
    const float* bo = (const float*)d_in[10];
    const int* mask = (const int*)d_in[11];

    float *KVPp, *KSPp, *KVp, *KSp;
    __half *hq, *hk, *hv, *Q16, *K16, *V16, *hA, *Wh;
    cudaGetSymbolAddress((void**)&hq, g_hq);
    cudaGetSymbolAddress((void**)&hk, g_hk);
    cudaGetSymbolAddress((void**)&hv, g_hv);
    cudaGetSymbolAddress((void**)&Q16, g_Q16);
    cudaGetSymbolAddress((void**)&K16, g_K16);
    cudaGetSymbolAddress((void**)&V16, g_V16);
    cudaGetSymbolAddress((void**)&hA, g_hA);
    cudaGetSymbolAddress((void**)&Wh, g_Wh);
    cudaGetSymbolAddress((void**)&KVPp, g_kvp);
    cudaGetSymbolAddress((void**)&KSPp, g_ksp);
    cudaGetSymbolAddress((void**)&KVp, g_kv);
    cudaGetSymbolAddress((void**)&KSp, g_ksum);

    cudaFuncSetAttribute(gemm_qkv, cudaFuncAttributeMaxDynamicSharedMemorySize, GEMM_DSMEM);
    cudaFuncSetAttribute(gemm_one, cudaFuncAttributeMaxDynamicSharedMemorySize, GEMM_DSMEM);

    dim3 ggrid3(DIMM / 128, MM / 128, 3);   // (8, 128, 3)
    dim3 ggrid(DIMM / 128, MM / 128);

    cvt_w4<<<dim3(1024, 4), 256>>>(Wq, Wk, Wv, Wo, Wh);
    cvt_acts<<<dim3(16384, 3), 256>>>(query, key, value, hq, hk, hv);
    // 3: merged Q/K/V projections  <-- likely profile slot
    gemm_qkv<<<ggrid3, GT, GEMM_DSMEM>>>(hq, hk, hv, Wh, bq, bk, bv, mask, Q16, K16, V16);
    kv_h<<<dim3(KVC, 64), 128>>>(K16, V16, KVPp, KSPp);
    reduce_kv<<<64, 256>>>(KVPp, KSPp, KVp, KSp);
    attn_kernel<<<dim3(32, 64), 256>>>(Q16, KVp, KSp, hA);
    gemm_one<<<ggrid, GT, GEMM_DSMEM>>>(hA, Wh + 3 * (size_t)DIMM * DIMM, bo, (float*)d_out);
}

// round 14
// speedup vs baseline: 1.2776x; 1.2776x over previous
#include <cuda_runtime.h>
#include <cuda_fp16.h>
#include <mma.h>
#include <cstdint>

using namespace nvcuda;

// Problem constants
#define BB 4
#define NN 4096
#define DIMM 1024
#define HH 16
#define HDD 64
#define MM (BB * NN)           // 16384 rows
#define KVC 16                 // kv partial chunks (256 rows each)

// ---------------- scratch (device globals; no allocation allowed) ----------
__device__ __half g_hq[(size_t)MM * DIMM];
__device__ __half g_hk[(size_t)MM * DIMM];
__device__ __half g_hv[(size_t)MM * DIMM];
__device__ __half g_Q16[(size_t)MM * DIMM];
__device__ __half g_K16[(size_t)MM * DIMM];
__device__ __half g_V16[(size_t)MM * DIMM];
__device__ __half g_hA[(size_t)MM * DIMM];
__device__ __half g_Wh[4 * DIMM * DIMM];
__device__ float  g_kvp[(size_t)KVC * BB * HH * HDD * HDD];
__device__ float  g_ksp[(size_t)KVC * BB * HH * HDD];
__device__ __half g_kv16[BB * HH * HDD * HDD];
__device__ float  g_ksum[BB * HH * HDD];

__device__ __forceinline__ void cp_async16(void* smem_ptr, const void* gmem_ptr) {
    unsigned int s = (unsigned int)__cvta_generic_to_shared(smem_ptr);
    asm volatile("cp.async.cg.shared.global [%0], [%1], 16;\n" :: "r"(s), "l"(gmem_ptr));
}

// ---------------- fp32 -> fp16 conversion (RN) ----------------
__global__ void cvt_w4(const float* __restrict__ W0, const float* __restrict__ W1,
                       const float* __restrict__ W2, const float* __restrict__ W3,
                       __half* __restrict__ dst) {
    const float* srcs[4] = {W0, W1, W2, W3};
    const int m = blockIdx.y;
    const float4* s = (const float4*)srcs[m];
    __half2* d = (__half2*)(dst + (size_t)m * DIMM * DIMM);
    int i = blockIdx.x * blockDim.x + threadIdx.x;
    if (i < (DIMM * DIMM) / 4) {
        float4 v = s[i];
        d[2 * i + 0] = __floats2half2_rn(v.x, v.y);
        d[2 * i + 1] = __floats2half2_rn(v.z, v.w);
    }
}

__global__ void cvt_acts(const float* __restrict__ A0, const float* __restrict__ A1,
                         const float* __restrict__ A2, __half* __restrict__ D0,
                         __half* __restrict__ D1, __half* __restrict__ D2) {
    const float* srcs[3] = {A0, A1, A2};
    __half* dsts[3] = {D0, D1, D2};
    const int m = blockIdx.y;
    const float4* s = (const float4*)srcs[m];
    __half2* d = (__half2*)dsts[m];
    int i = blockIdx.x * blockDim.x + threadIdx.x;
    if (i < (MM * DIMM) / 4) {
        float4 v = s[i];
        d[2 * i + 0] = __floats2half2_rn(v.x, v.y);
        d[2 * i + 1] = __floats2half2_rn(v.z, v.w);
    }
}

// ==== fp16 GEMM (R12 shape): 128x128 block, 8 warps, 32x64 tile, KC=64 ====
#define KC 64
#define HPAD 72
#define HTILE (128 * HPAD)
#define HSTAGE (2 * HTILE)
#define GEMM_DSMEM (2 * HSTAGE * 2)        // 73728 bytes

extern __shared__ __align__(16) __half dsm_h[];

struct GemmCore {
    wmma::fragment<wmma::accumulator, 16, 16, 16, float> acc[2][4];
    int t, w, wm, wn;

    __device__ __forceinline__ void init(int tid) {
        t = tid; w = t >> 5; wm = w >> 1; wn = w & 1;
#pragma unroll
        for (int i = 0; i < 2; i++)
#pragma unroll
            for (int j = 0; j < 4; j++)
                wmma::fill_fragment(acc[i][j], 0.0f);
    }

    __device__ __forceinline__ void load_chunk(const __half* Abase, const __half* Bbase,
                                               int kc, int s) {
        __half* As = dsm_h + s * HSTAGE;
        __half* Bs = As + HTILE;
        const int k0 = kc * KC;
#pragma unroll
        for (int j = 0; j < 4; j++) {
            int u = t + j * 256;
            int row = u >> 3;
            int c8 = (u & 7) * 8;
            cp_async16(&As[row * HPAD + c8], Abase + (size_t)row * DIMM + k0 + c8);
            cp_async16(&Bs[row * HPAD + c8], Bbase + (size_t)row * DIMM + k0 + c8);
        }
    }

    __device__ __forceinline__ void mainloop(const __half* Abase, const __half* Bbase) {
        load_chunk(Abase, Bbase, 0, 0);
        asm volatile("cp.async.commit_group;\n");
        const int NCH = DIMM / KC;   // 16
        for (int i = 0; i < NCH; i++) {
            const int s = i & 1;
            if (i + 1 < NCH) {
                load_chunk(Abase, Bbase, i + 1, s ^ 1);
                asm volatile("cp.async.commit_group;\n");
                asm volatile("cp.async.wait_group 1;\n");
            } else {
                asm volatile("cp.async.wait_group 0;\n");
            }
            __syncthreads();

            const __half* As = dsm_h + s * HSTAGE;
            const __half* Bs = As + HTILE;
#pragma unroll
            for (int kk = 0; kk < KC; kk += 16) {
                wmma::fragment<wmma::matrix_a, 16, 16, 16, __half, wmma::row_major> af[2];
                wmma::fragment<wmma::matrix_b, 16, 16, 16, __half, wmma::col_major> bf[4];
#pragma unroll
                for (int x = 0; x < 2; x++)
                    wmma::load_matrix_sync(af[x], As + (wm * 32 + x * 16) * HPAD + kk, HPAD);
#pragma unroll
                for (int y = 0; y < 4; y++)
                    wmma::load_matrix_sync(bf[y], Bs + (wn * 64 + y * 16) * HPAD + kk, HPAD);
#pragma unroll
                for (int x = 0; x < 2; x++)
#pragma unroll
                    for (int y = 0; y < 4; y++)
                        wmma::mma_sync(acc[x][y], af[x], bf[y], acc[x][y]);
            }
            __syncthreads();
        }
    }

    __device__ __forceinline__ void epilogue(const float* bias, const int* mask,
                                             float* Cf, __half* Ch, int do_relu,
                                             int m0, int n0) {
        float* Ct = (float*)dsm_h;
#pragma unroll
        for (int half = 0; half < 2; half++) {
            if ((wm >> 1) == half) {
                const int wml = wm & 1;
#pragma unroll
                for (int x = 0; x < 2; x++)
#pragma unroll
                    for (int y = 0; y < 4; y++)
                        wmma::store_matrix_sync(Ct + (wml * 32 + x * 16) * 132 + wn * 64 + y * 16,
                                                acc[x][y], 132, wmma::mem_row_major);
            }
            __syncthreads();
#pragma unroll
            for (int i = 0; i < 8; i++) {
                int u = t + i * 256;
                int r = u >> 5;
                int c = (u & 31) * 4;
                int row = m0 + half * 64 + r;
                float4 v = *(float4*)(Ct + r * 132 + c);
                v.x += bias[n0 + c + 0];
                v.y += bias[n0 + c + 1];
                v.z += bias[n0 + c + 2];
                v.w += bias[n0 + c + 3];
                if (do_relu) {
                    v.x = fmaxf(v.x, 0.0f); v.y = fmaxf(v.y, 0.0f);
                    v.z = fmaxf(v.z, 0.0f); v.w = fmaxf(v.w, 0.0f);
                }
                if (mask != nullptr && mask[row] != 0) {
                    v.x = 0.0f; v.y = 0.0f; v.z = 0.0f; v.w = 0.0f;
                }
                if (Ch != nullptr) {
                    __half2* p = (__half2*)(Ch + (size_t)row * DIMM + n0 + c);
                    p[0] = __floats2half2_rn(v.x, v.y);
                    p[1] = __floats2half2_rn(v.z, v.w);
                } else {
                    *(float4*)(Cf + (size_t)row * DIMM + n0 + c) = v;
                }
            }
            __syncthreads();
        }
    }
};

__global__ void __launch_bounds__(256, 2)
gemm_qkv(const __half* __restrict__ hq, const __half* __restrict__ hk,
         const __half* __restrict__ hv, const __half* __restrict__ Wh,
         const float* __restrict__ bq, const float* __restrict__ bk,
         const float* __restrict__ bv, const int* __restrict__ mask,
         __half* __restrict__ Q16, __half* __restrict__ K16, __half* __restrict__ V16) {
    const int z = blockIdx.z;
    const __half* A = (z == 0) ? hq : (z == 1) ? hk : hv;
    const __half* W = Wh + (size_t)z * DIMM * DIMM;
    const float* bias = (z == 0) ? bq : (z == 1) ? bk : bv;
    const int* mk = (z == 1) ? mask : nullptr;
    __half* out = (z == 0) ? Q16 : (z == 1) ? K16 : V16;
    const int do_relu = (z < 2);

    GemmCore g;
    g.init(threadIdx.x);
    const int n0 = blockIdx.x * 128;
    const int m0 = blockIdx.y * 128;
    g.mainloop(A + (size_t)m0 * DIMM, W + (size_t)n0 * DIMM);
    g.epilogue(bias, mk, nullptr, out, do_relu, m0, n0);
}

__global__ void __launch_bounds__(256, 2)
gemm_one(const __half* __restrict__ A, const __half* __restrict__ W,
         const float* __restrict__ bias, float* __restrict__ Cf) {
    GemmCore g;
    g.init(threadIdx.x);
    const int n0 = blockIdx.x * 128;
    const int m0 = blockIdx.y * 128;
    g.mainloop(A + (size_t)m0 * DIMM, W + (size_t)n0 * DIMM);
    g.epilogue(bias, nullptr, Cf, nullptr, 0, m0, n0);
}

// ---- kv partials via fp16 WMMA: kvp[c][bh] = K_c^T @ V_c (64x64x256) -----
#define KVPAD 72
__global__ void __launch_bounds__(128)
kv_h(const __half* __restrict__ K, const __half* __restrict__ V,
     float* __restrict__ kvp, float* __restrict__ ksp) {
    __shared__ __align__(16) __half Ks[128][KVPAD];
    __shared__ __align__(16) __half Vs[128][KVPAD];
    __shared__ float ksb[128];

    const int bh = blockIdx.y;
    const int b = bh >> 4, h = bh & 15;
    const int chunk = blockIdx.x;
    const int t = threadIdx.x;
    const int w = t >> 5;
    const int d0 = w * 16;
    const int dcol = t & 63, rhalf = t >> 6;

    wmma::fragment<wmma::accumulator, 16, 16, 16, float> acc[4];
#pragma unroll
    for (int e = 0; e < 4; e++) wmma::fill_fragment(acc[e], 0.0f);
    float ksacc = 0.0f;

#pragma unroll
    for (int sub = 0; sub < 2; sub++) {
        const int n0 = chunk * 256 + sub * 128;
#pragma unroll
        for (int j = 0; j < 8; j++) {
            int u = t + j * 128;
            int row = u >> 3;
            int c8 = (u & 7) * 8;
            const size_t goff = (size_t)(b * NN + n0 + row) * DIMM + h * HDD + c8;
            cp_async16(&Ks[row][c8], K + goff);
            cp_async16(&Vs[row][c8], V + goff);
        }
        asm volatile("cp.async.commit_group;\n");
        asm volatile("cp.async.wait_group 0;\n");
        __syncthreads();

#pragma unroll 16
        for (int r = rhalf * 64; r < rhalf * 64 + 64; r++)
            ksacc += __half2float(Ks[r][dcol]);

#pragma unroll
        for (int ns = 0; ns < 128; ns += 16) {
            wmma::fragment<wmma::matrix_a, 16, 16, 16, __half, wmma::col_major> a;
            wmma::load_matrix_sync(a, &Ks[ns][d0], KVPAD);
#pragma unroll
            for (int e = 0; e < 4; e++) {
                wmma::fragment<wmma::matrix_b, 16, 16, 16, __half, wmma::row_major> bfr;
                wmma::load_matrix_sync(bfr, &Vs[ns][e * 16], KVPAD);
                wmma::mma_sync(acc[e], a, bfr, acc[e]);
            }
        }
        __syncthreads();
    }

    float* dst = kvp + ((size_t)chunk * 64 + bh) * (HDD * HDD);
#pragma unroll
    for (int e = 0; e < 4; e++)
        wmma::store_matrix_sync(dst + d0 * 64 + e * 16, acc[e], 64, wmma::mem_row_major);

    ksb[t] = ksacc;
    __syncthreads();
    if (t < 64) ksp[((size_t)chunk * 64 + bh) * HDD + t] = ksb[t] + ksb[t + 64];
}

// ---- reduce partials: kv -> fp16, ksum -> fp32 ----
__global__ void __launch_bounds__(256)
reduce_kv(const float* __restrict__ kvp, const float* __restrict__ ksp,
          __half* __restrict__ kv16, float* __restrict__ ksum) {
    const int bh = blockIdx.x;
    const int t = threadIdx.x;
    for (int i = t; i < HDD * HDD; i += 256) {
        float s = 0.0f;
#pragma unroll
        for (int c = 0; c < KVC; c++)
            s += kvp[((size_t)c * 64 + bh) * (HDD * HDD) + i];
        kv16[(size_t)bh * (HDD * HDD) + i] = __float2half_rn(s);
    }
    if (t < 64) {
        float s = 0.0f;
#pragma unroll
        for (int c = 0; c < KVC; c++)
            s += ksp[((size_t)c * 64 + bh) * HDD + t];
        ksum[bh * HDD + t] = s;
    }
}

// ---- WMMA attn: out = (Q @ kv) / (Q.ksum + eps), fp16 in/out --------------
// block: (128-row chunk, bh), 128 threads (4 warps, each 32 rows).
#define APAD 72
#define ATTN_OFF_KV 18432                       // after Q tile (128*72*2)
#define ATTN_OFF_KSS 34816                      // after C tile (128*68*4)
#define ATTN_OFF_DEN 35072
#define ATTN_DSMEM 35584

__global__ void __launch_bounds__(128)
attn_h(const __half* __restrict__ Q, const __half* __restrict__ kv16,
       const float* __restrict__ ksum, __half* __restrict__ out) {
    char* dyn = (char*)dsm_h;
    __half* Qs = (__half*)dyn;                      // [128][APAD]
    __half* KVs = (__half*)(dyn + ATTN_OFF_KV);     // [64][APAD]
    float* Cs = (float*)dyn;                        // [128][68] (reuse after MMA)
    float* kss = (float*)(dyn + ATTN_OFF_KSS);      // [64]
    float* dn = (float*)(dyn + ATTN_OFF_DEN);       // [128]

    const int bh = blockIdx.y;
    const int b = bh >> 4, h = bh & 15;
    const int nbase = blockIdx.x * 128;
    const int t = threadIdx.x;
    const int w = t >> 5;

    // load Q tile 128x64 (8 chunks of 16B per row) and kv 64x64
#pragma unroll
    for (int j = 0; j < 8; j++) {
        int u = t + j * 128;
        int row = u >> 3;
        int c8 = (u & 7) * 8;
        cp_async16(&Qs[row * APAD + c8],
                   Q + (size_t)(b * NN + nbase + row) * DIMM + h * HDD + c8);
    }
#pragma unroll
    for (int j = 0; j < 4; j++) {
        int u = t + j * 128;
        int row = u >> 3;
        int c8 = (u & 7) * 8;
        cp_async16(&KVs[row * APAD + c8], kv16 + (size_t)bh * 4096 + row * 64 + c8);
    }
    if (t < 64) kss[t] = ksum[bh * 64 + t];
    asm volatile("cp.async.commit_group;\n");
    asm volatile("cp.async.wait_group 0;\n");
    __syncthreads();

    // denominator: thread t = row t
    {
        float p = 0.0f;
#pragma unroll 16
        for (int d = 0; d < 64; d++)
            p += __half2float(Qs[t * APAD + d]) * kss[d];
        dn[t] = 1.0f / (p + 1e-6f);
    }

    // numerator MMA: warp w -> rows w*32..w*32+31
    wmma::fragment<wmma::accumulator, 16, 16, 16, float> acc[2][4];
#pragma unroll
    for (int x = 0; x < 2; x++)
#pragma unroll
        for (int y = 0; y < 4; y++)
            wmma::fill_fragment(acc[x][y], 0.0f);
#pragma unroll
    for (int k = 0; k < 64; k += 16) {
        wmma::fragment<wmma::matrix_a, 16, 16, 16, __half, wmma::row_major> af[2];
        wmma::fragment<wmma::matrix_b, 16, 16, 16, __half, wmma::row_major> bf[4];
#pragma unroll
        for (int x = 0; x < 2; x++)
            wmma::load_matrix_sync(af[x], Qs + (w * 32 + x * 16) * APAD + k, APAD);
#pragma unroll
        for (int y = 0; y < 4; y++)
            wmma::load_matrix_sync(bf[y], KVs + k * APAD + y * 16, APAD);
#pragma unroll
        for (int x = 0; x < 2; x++)
#pragma unroll
            for (int y = 0; y < 4; y++)
                wmma::mma_sync(acc[x][y], af[x], bf[y], acc[x][y]);
    }
    __syncthreads();   // Qs/KVs reads done; safe to overwrite with Cs

#pragma unroll
    for (int x = 0; x < 2; x++)
#pragma unroll
        for (int y = 0; y < 4; y++)
            wmma::store_matrix_sync(Cs + (w * 32 + x * 16) * 68 + y * 16,
                                    acc[x][y], 68, wmma::mem_row_major);
    __syncthreads();

    // scale rows and emit fp16 (half2 stores)
#pragma unroll
    for (int i = 0; i < 32; i++) {
        int u = t + i * 128;
        int row = u >> 5;
        int e2 = (u & 31) * 2;
        float sc = dn[row];
        __half2 hv2 = __floats2half2_rn(Cs[row * 68 + e2] * sc, Cs[row * 68 + e2 + 1] * sc);
        *(__half2*)(out + (size_t)(b * NN + nbase + row) * DIMM + h * HDD + e2) = hv2;
    }
}

// ---------------- launch ----------------
extern "C" void kernel_launch(void* const* d_in, const int* in_sizes, int n_in,
                              void* d_out, int out_size) {
    const float* query = (const float*)d_in[0];
    const float* key   = (const float*)d_in[1];
    const float* value = (const float*)d_in[2];
    const float* Wq = (const float*)d_in[3];
    const float* bq = (const float*)d_in[4];
    const float* Wk = (const float*)d_in[5];
    const float* bk = (const float*)d_in[6];
    const float* Wv = (const float*)d_in[7];
    const float* bv = (const float*)d_in[8];
    const float* Wo = (const float*)d_in[9];
    const float* bo = (const float*)d_in[10];
    const int* mask = (const int*)d_in[11];

    float *KVPp, *KSPp, *KSp;
    __half *hq, *hk, *hv, *Q16, *K16, *V16, *hA, *Wh, *KV16;
    cudaGetSymbolAddress((void**)&hq, g_hq);
    cudaGetSymbolAddress((void**)&hk, g_hk);
    cudaGetSymbolAddress((void**)&hv, g_hv);
    cudaGetSymbolAddress((void**)&Q16, g_Q16);
    cudaGetSymbolAddress((void**)&K16, g_K16);
    cudaGetSymbolAddress((void**)&V16, g_V16);
    cudaGetSymbolAddress((void**)&hA, g_hA);
    cudaGetSymbolAddress((void**)&Wh, g_Wh);
    cudaGetSymbolAddress((void**)&KVPp, g_kvp);
    cudaGetSymbolAddress((void**)&KSPp, g_ksp);
    cudaGetSymbolAddress((void**)&KV16, g_kv16);
    cudaGetSymbolAddress((void**)&KSp, g_ksum);

    cudaFuncSetAttribute(gemm_qkv, cudaFuncAttributeMaxDynamicSharedMemorySize, GEMM_DSMEM);
    cudaFuncSetAttribute(gemm_one, cudaFuncAttributeMaxDynamicSharedMemorySize, GEMM_DSMEM);

    dim3 ggrid3(DIMM / 128, MM / 128, 3);   // (8, 128, 3)
    dim3 ggrid(DIMM / 128, MM / 128);

    cvt_w4<<<dim3(1024, 4), 256>>>(Wq, Wk, Wv, Wo, Wh);
    cvt_acts<<<dim3(16384, 3), 256>>>(query, key, value, hq, hk, hv);
    gemm_qkv<<<ggrid3, 256, GEMM_DSMEM>>>(hq, hk, hv, Wh, bq, bk, bv, mask, Q16, K16, V16);
    kv_h<<<dim3(KVC, 64), 128>>>(K16, V16, KVPp, KSPp);
    reduce_kv<<<64, 256>>>(KVPp, KSPp, KV16, KSp);
    // 6: WMMA attention  <-- ncu profile slot
    attn_h<<<dim3(NN / 128, 64), 128, ATTN_DSMEM>>>(Q16, KV16, KSp, hA);
    gemm_one<<<ggrid, 256, GEMM_DSMEM>>>(hA, Wh + 3 * (size_t)DIMM * DIMM, bo, (float*)d_out);
}